// round 2
// baseline (speedup 1.0000x reference)
#include <cuda_runtime.h>

// 4-layer LSTM (H=50, T=10, F=5) + Dense(50) + Dense(1,sigmoid), fully fused.
// One block owns NB=8 batch elements for the entire network.
// Thread t: j = t>>3 (hidden unit 0..49), b = t&7 (local batch 0..7).
//
// Round-1 change: inner dot-products use packed fma.rn.f32x2 (FFMA2) over
// adjacent K pairs. 16B smem loads are read as ulonglong2 (two f32x2 lanes),
// so no pack instructions are needed; fma-pipe instruction count halves.
//
// Bank-conflict design (unchanged):
//   row pitch 52 floats == 20 banks (mod 32); seq per-batch stride 572 == 28.
//   U/W reads broadcast x8 across batch lanes.

#define NB      8
#define TT      10
#define HID     50
#define KP      52            // padded K
#define NK4     13            // KP/4 (16B chunks)
#define SEQROWS 11            // 10 timesteps + 1 pad row
#define SEQSTR  (SEQROWS*KP)  // 572 floats per batch element
#define THREADS 400

// smem layout (float offsets)
#define OFF_WT   0            // 200 x 52 transposed input weights
#define OFF_UT   10400        // 200 x 52 transposed recurrent weights
#define OFF_BIAS 20800        // 208
#define OFF_WD2  21008        // 52 : Wd2[50] + bd2
#define OFF_SEQ  21060        // NB * 572 = 4576
#define OFF_H    25636        // NB * 52  = 416
#define SMEM_FLOATS 26052
#define SMEM_BYTES  (SMEM_FLOATS * 4)

typedef unsigned long long u64;

struct Params {
    const float* x;
    const float* W[4];
    const float* U[4];
    const float* bb[4];
    const float* Wd1;
    const float* bd1;
    const float* Wd2;
    const float* bd2;
    float* out;
    int B;
};

__device__ __forceinline__ float sigmoid_(float v) {
    return __fdividef(1.0f, 1.0f + __expf(-v));
}

__device__ __forceinline__ float tanh_(float v) {
    float e = __expf(-2.0f * fabsf(v));
    float t = __fdividef(1.0f - e, 1.0f + e);
    return copysignf(t, v);
}

// Packed f32x2 fma: acc = a*b + acc (per 32-bit lane). sm_100+/PTX 8.6+.
__device__ __forceinline__ void ffma2(u64& acc, u64 a, u64 b) {
    asm("fma.rn.f32x2 %0, %1, %2, %0;" : "+l"(acc) : "l"(a), "l"(b));
}

__device__ __forceinline__ float hsum2(u64 v) {
    float lo, hi;
    asm("mov.b64 {%0, %1}, %2;" : "=f"(lo), "=f"(hi) : "l"(v));
    return lo + hi;
}

// One LSTM layer over all T steps for this block's batch tile.
// NKIN4: number of 16B K-iterations for the input (x@W) part.
template <int NKIN4>
__device__ __forceinline__ void lstm_steps(float* __restrict__ seq,
                                           float* __restrict__ hbuf,
                                           const float* __restrict__ Wt,
                                           const float* __restrict__ Ut,
                                           const float* __restrict__ bias,
                                           int b, int j, bool write_seq) {
    const ulonglong2* Wt2 = (const ulonglong2*)Wt;  // index = 16B chunk
    const ulonglong2* Ut2 = (const ulonglong2*)Ut;
    const ulonglong2* h2  = (const ulonglong2*)hbuf;
    const ulonglong2* sq2 = (const ulonglong2*)seq;

    const int rI = (0 * HID + j) * NK4;
    const int rF = (1 * HID + j) * NK4;
    const int rG = (2 * HID + j) * NK4;
    const int rO = (3 * HID + j) * NK4;

    const float bI = bias[j];
    const float bF = bias[HID + j];
    const float bG = bias[2 * HID + j];
    const float bO = bias[3 * HID + j];

    float c = 0.0f;

#pragma unroll 1
    for (int t = 0; t < TT; t++) {
        u64 aI0 = 0, aI1 = 0, aF0 = 0, aF1 = 0;
        u64 aG0 = 0, aG1 = 0, aO0 = 0, aO1 = 0;

        const ulonglong2* xin = sq2 + b * (SEQROWS * NK4) + t * NK4;
#pragma unroll
        for (int k4 = 0; k4 < NKIN4; k4++) {
            ulonglong2 xv = xin[k4];
            ulonglong2 wI = Wt2[rI + k4];
            ulonglong2 wF = Wt2[rF + k4];
            ulonglong2 wG = Wt2[rG + k4];
            ulonglong2 wO = Wt2[rO + k4];
            ffma2(aI0, xv.x, wI.x); ffma2(aI1, xv.y, wI.y);
            ffma2(aF0, xv.x, wF.x); ffma2(aF1, xv.y, wF.y);
            ffma2(aG0, xv.x, wG.x); ffma2(aG1, xv.y, wG.y);
            ffma2(aO0, xv.x, wO.x); ffma2(aO1, xv.y, wO.y);
        }
#pragma unroll
        for (int k4 = 0; k4 < NK4; k4++) {
            ulonglong2 hv = h2[b * NK4 + k4];
            ulonglong2 uI = Ut2[rI + k4];
            ulonglong2 uF = Ut2[rF + k4];
            ulonglong2 uG = Ut2[rG + k4];
            ulonglong2 uO = Ut2[rO + k4];
            ffma2(aI0, hv.x, uI.x); ffma2(aI1, hv.y, uI.y);
            ffma2(aF0, hv.x, uF.x); ffma2(aF1, hv.y, uF.y);
            ffma2(aG0, hv.x, uG.x); ffma2(aG1, hv.y, uG.y);
            ffma2(aO0, hv.x, uO.x); ffma2(aO1, hv.y, uO.y);
        }
        __syncthreads();  // all reads of hbuf/seq done before overwrite

        float gi = sigmoid_(bI + hsum2(aI0) + hsum2(aI1));
        float gf = sigmoid_(bF + hsum2(aF0) + hsum2(aF1));
        float gg = tanh_   (bG + hsum2(aG0) + hsum2(aG1));
        float go = sigmoid_(bO + hsum2(aO0) + hsum2(aO1));
        c = gf * c + gi * gg;
        float h = go * tanh_(c);

        hbuf[b * KP + j] = h;
        if (write_seq) seq[b * SEQSTR + t * KP + j] = h;
        __syncthreads();  // writes visible before next step's reads
    }
}

extern __shared__ float smem[];

__global__ void __launch_bounds__(THREADS, 2) lstm_fused(Params p) {
    float* Wt   = smem + OFF_WT;
    float* Ut   = smem + OFF_UT;
    float* bias = smem + OFF_BIAS;
    float* wd2  = smem + OFF_WD2;
    float* seq  = smem + OFF_SEQ;
    float* hbuf = smem + OFF_H;

    const int tid = threadIdx.x;
    const int j = tid >> 3;   // 0..49
    const int b = tid & 7;    // 0..7
    const long bg = (long)blockIdx.x * NB + b;
    const bool valid = bg < p.B;

    // ---- load x into padded seq buffer (zeros in pads) ----
    for (int i = tid; i < NB * SEQSTR; i += THREADS) {
        int bb = i / SEQSTR;
        int r  = i - bb * SEQSTR;
        int t  = r / KP;
        int k  = r - t * KP;
        long bgg = (long)blockIdx.x * NB + bb;
        float v = 0.0f;
        if (t < TT && k < 5 && bgg < p.B) v = p.x[(bgg * TT + t) * 5 + k];
        seq[i] = v;
    }

    // ---- 4 LSTM layers ----
#pragma unroll 1
    for (int layer = 0; layer < 4; layer++) {
        const int Kin = (layer == 0) ? 5 : HID;
        const float* W = p.W[layer];
        const float* U = p.U[layer];
        const float* bv = p.bb[layer];

        __syncthreads();  // prior layer's reads complete (also covers x-load)
        for (int i = tid; i < 10400; i += THREADS) { Wt[i] = 0.0f; Ut[i] = 0.0f; }
        for (int i = tid; i < NB * KP; i += THREADS) hbuf[i] = 0.0f;
        __syncthreads();
        for (int i = tid; i < Kin * 200; i += THREADS) {
            int k = i / 200, n = i - k * 200;
            Wt[n * KP + k] = W[i];           // transposed, coalesced global read
        }
        for (int i = tid; i < HID * 200; i += THREADS) {
            int k = i / 200, n = i - k * 200;
            Ut[n * KP + k] = U[i];
        }
        for (int i = tid; i < 200; i += THREADS) bias[i] = bv[i];
        __syncthreads();

        if (layer == 0)
            lstm_steps<2>(seq, hbuf, Wt, Ut, bias, b, j, true);
        else if (layer < 3)
            lstm_steps<NK4>(seq, hbuf, Wt, Ut, bias, b, j, true);
        else
            lstm_steps<NK4>(seq, hbuf, Wt, Ut, bias, b, j, false);  // only last h
    }

    // ---- Dense(50) + Dense(1, sigmoid) ----
    for (int i = tid; i < 10400; i += THREADS) Wt[i] = 0.0f;
    __syncthreads();
    for (int i = tid; i < HID * HID; i += THREADS) {
        int k = i / HID, m = i - k * HID;
        Wt[m * KP + k] = p.Wd1[i];
    }
    for (int i = tid; i < HID; i += THREADS) {
        bias[i] = p.bd1[i];
        wd2[i]  = p.Wd2[i];
    }
    if (tid == 0) wd2[HID] = p.bd2[0];
    __syncthreads();

    {
        const ulonglong2* Wt2 = (const ulonglong2*)Wt;
        const ulonglong2* h2  = (const ulonglong2*)hbuf;
        u64 a0 = 0, a1 = 0;
#pragma unroll
        for (int k4 = 0; k4 < NK4; k4++) {
            ulonglong2 hv = h2[b * NK4 + k4];
            ulonglong2 wv = Wt2[j * NK4 + k4];
            ffma2(a0, hv.x, wv.x);
            ffma2(a1, hv.y, wv.y);
        }
        seq[b * SEQSTR + j] = bias[j] + hsum2(a0) + hsum2(a1);  // dense1 out
    }
    __syncthreads();

    if (j == 0 && valid) {
        float acc = wd2[HID];  // bd2
#pragma unroll
        for (int m = 0; m < HID; m++) acc += seq[b * SEQSTR + m] * wd2[m];
        p.out[bg] = sigmoid_(acc);
    }
}

extern "C" void kernel_launch(void* const* d_in, const int* in_sizes, int n_in,
                              void* d_out, int out_size) {
    Params p;
    p.x = (const float*)d_in[0];
    p.W[0] = (const float*)d_in[1];  p.U[0] = (const float*)d_in[2];  p.bb[0] = (const float*)d_in[3];
    p.W[1] = (const float*)d_in[4];  p.U[1] = (const float*)d_in[5];  p.bb[1] = (const float*)d_in[6];
    p.W[2] = (const float*)d_in[7];  p.U[2] = (const float*)d_in[8];  p.bb[2] = (const float*)d_in[9];
    p.W[3] = (const float*)d_in[10]; p.U[3] = (const float*)d_in[11]; p.bb[3] = (const float*)d_in[12];
    p.Wd1 = (const float*)d_in[13];
    p.bd1 = (const float*)d_in[14];
    p.Wd2 = (const float*)d_in[15];
    p.bd2 = (const float*)d_in[16];
    p.out = (float*)d_out;
    p.B = in_sizes[0] / (TT * 5);

    cudaFuncSetAttribute(lstm_fused, cudaFuncAttributeMaxDynamicSharedMemorySize, SMEM_BYTES);
    int grid = (p.B + NB - 1) / NB;
    lstm_fused<<<grid, THREADS, SMEM_BYTES>>>(p);
}

// round 7
// speedup vs baseline: 6.3013x; 6.3013x over previous
#include <cuda_runtime.h>

// 4-layer LSTM (H=50, T=10, F=5) + Dense(50) + Dense(1,sigmoid), fully fused.
// One block owns NB=8 batch elements for the entire network.
// Thread t: j = t>>3 (hidden unit 0..49), b = t&7 (local batch 0..7).
//
// Anti-spill design (untested across 5 broker timeouts): bounded unroll (2),
// one f32x2 accumulator per gate, weights staged two gates at a time.
// Peak live registers ~60 < 80 cap -> no local memory traffic.
//
// Bank-conflict design:
//   row pitch 52 floats == 20 banks (mod 32); seq per-batch stride 572 == 28.
//   Weight reads broadcast x8 across batch lanes.

#define NB      8
#define TT      10
#define HID     50
#define KP      52            // padded K
#define NK4     13            // KP/4 (16B chunks)
#define SEQROWS 11            // 10 timesteps + 1 pad row
#define SEQSTR  (SEQROWS*KP)  // 572 floats per batch element
#define THREADS 400

// smem layout (float offsets)
#define OFF_WT   0            // 200 x 52 transposed input weights
#define OFF_UT   10400        // 200 x 52 transposed recurrent weights
#define OFF_BIAS 20800        // 208
#define OFF_WD2  21008        // 52 : Wd2[50] + bd2
#define OFF_SEQ  21060        // NB * 572 = 4576
#define OFF_H    25636        // NB * 52  = 416
#define SMEM_FLOATS 26052
#define SMEM_BYTES  (SMEM_FLOATS * 4)

typedef unsigned long long u64;

struct Params {
    const float* x;
    const float* W[4];
    const float* U[4];
    const float* bb[4];
    const float* Wd1;
    const float* bd1;
    const float* Wd2;
    const float* bd2;
    float* out;
    int B;
};

__device__ __forceinline__ float sigmoid_(float v) {
    return __fdividef(1.0f, 1.0f + __expf(-v));
}

__device__ __forceinline__ float tanh_(float v) {
    float e = __expf(-2.0f * fabsf(v));
    float t = __fdividef(1.0f - e, 1.0f + e);
    return copysignf(t, v);
}

// Packed f32x2 fma: acc = a*b + acc (per 32-bit lane). sm_100+/PTX 8.6+.
__device__ __forceinline__ void ffma2(u64& acc, u64 a, u64 b) {
    asm("fma.rn.f32x2 %0, %1, %2, %0;" : "+l"(acc) : "l"(a), "l"(b));
}

__device__ __forceinline__ float hsum2(u64 v) {
    float lo, hi;
    asm("mov.b64 {%0, %1}, %2;" : "=f"(lo), "=f"(hi) : "l"(v));
    return lo + hi;
}

// Accumulate one 16B input chunk against 4 gate weight rows.
// Two weight vectors live at a time -> low register pressure.
__device__ __forceinline__ void gate_fma4(u64& aI, u64& aF, u64& aG, u64& aO,
                                          ulonglong2 xv,
                                          const ulonglong2* __restrict__ mI,
                                          const ulonglong2* __restrict__ mF,
                                          const ulonglong2* __restrict__ mG,
                                          const ulonglong2* __restrict__ mO,
                                          int k4) {
    ulonglong2 w0 = mI[k4];
    ulonglong2 w1 = mF[k4];
    ffma2(aI, xv.x, w0.x); ffma2(aF, xv.x, w1.x);
    ffma2(aI, xv.y, w0.y); ffma2(aF, xv.y, w1.y);
    ulonglong2 w2 = mG[k4];
    ulonglong2 w3 = mO[k4];
    ffma2(aG, xv.x, w2.x); ffma2(aO, xv.x, w3.x);
    ffma2(aG, xv.y, w2.y); ffma2(aO, xv.y, w3.y);
}

// One LSTM layer over all T steps for this block's batch tile.
// NKIN4: number of 16B K-iterations for the input (x@W) part.
template <int NKIN4>
__device__ __forceinline__ void lstm_steps(float* __restrict__ seq,
                                           float* __restrict__ hbuf,
                                           const float* __restrict__ Wt,
                                           const float* __restrict__ Ut,
                                           const float* __restrict__ bias,
                                           int b, int j, bool write_seq) {
    const ulonglong2* h2  = (const ulonglong2*)hbuf;
    const ulonglong2* sq2 = (const ulonglong2*)seq;

    const ulonglong2* WI = (const ulonglong2*)Wt + (0 * HID + j) * NK4;
    const ulonglong2* WF = (const ulonglong2*)Wt + (1 * HID + j) * NK4;
    const ulonglong2* WG = (const ulonglong2*)Wt + (2 * HID + j) * NK4;
    const ulonglong2* WO = (const ulonglong2*)Wt + (3 * HID + j) * NK4;
    const ulonglong2* UI = (const ulonglong2*)Ut + (0 * HID + j) * NK4;
    const ulonglong2* UF = (const ulonglong2*)Ut + (1 * HID + j) * NK4;
    const ulonglong2* UG = (const ulonglong2*)Ut + (2 * HID + j) * NK4;
    const ulonglong2* UO = (const ulonglong2*)Ut + (3 * HID + j) * NK4;

    const float bI = bias[j];
    const float bF = bias[HID + j];
    const float bG = bias[2 * HID + j];
    const float bO = bias[3 * HID + j];

    float c = 0.0f;

#pragma unroll 1
    for (int t = 0; t < TT; t++) {
        u64 aI = 0, aF = 0, aG = 0, aO = 0;

        const ulonglong2* xin = sq2 + b * (SEQROWS * NK4) + t * NK4;
#pragma unroll 2
        for (int k4 = 0; k4 < NKIN4; k4++) {
            ulonglong2 xv = xin[k4];
            gate_fma4(aI, aF, aG, aO, xv, WI, WF, WG, WO, k4);
        }
        const ulonglong2* hin = h2 + b * NK4;
#pragma unroll 2
        for (int k4 = 0; k4 < NK4; k4++) {
            ulonglong2 hv = hin[k4];
            gate_fma4(aI, aF, aG, aO, hv, UI, UF, UG, UO, k4);
        }
        __syncthreads();  // all reads of hbuf/seq done before overwrite

        float gi = sigmoid_(bI + hsum2(aI));
        float gf = sigmoid_(bF + hsum2(aF));
        float gg = tanh_   (bG + hsum2(aG));
        float go = sigmoid_(bO + hsum2(aO));
        c = gf * c + gi * gg;
        float h = go * tanh_(c);

        hbuf[b * KP + j] = h;
        if (write_seq) seq[b * SEQSTR + t * KP + j] = h;
        __syncthreads();  // writes visible before next step's reads
    }
}

extern __shared__ float smem[];

__global__ void __launch_bounds__(THREADS, 2) lstm_fused(Params p) {
    float* Wt   = smem + OFF_WT;
    float* Ut   = smem + OFF_UT;
    float* bias = smem + OFF_BIAS;
    float* wd2  = smem + OFF_WD2;
    float* seq  = smem + OFF_SEQ;
    float* hbuf = smem + OFF_H;

    const int tid = threadIdx.x;
    const int j = tid >> 3;   // 0..49
    const int b = tid & 7;    // 0..7
    const long bg = (long)blockIdx.x * NB + b;
    const bool valid = bg < p.B;

    // ---- load x into padded seq buffer (zeros in pads) ----
    for (int i = tid; i < NB * SEQSTR; i += THREADS) {
        int bb = i / SEQSTR;
        int r  = i - bb * SEQSTR;
        int t  = r / KP;
        int k  = r - t * KP;
        long bgg = (long)blockIdx.x * NB + bb;
        float v = 0.0f;
        if (t < TT && k < 5 && bgg < p.B) v = p.x[(bgg * TT + t) * 5 + k];
        seq[i] = v;
    }

    // ---- 4 LSTM layers ----
#pragma unroll 1
    for (int layer = 0; layer < 4; layer++) {
        const int Kin = (layer == 0) ? 5 : HID;
        const float* W = p.W[layer];
        const float* U = p.U[layer];
        const float* bv = p.bb[layer];

        __syncthreads();  // prior layer's reads complete (also covers x-load)
        for (int i = tid; i < 10400; i += THREADS) { Wt[i] = 0.0f; Ut[i] = 0.0f; }
        for (int i = tid; i < NB * KP; i += THREADS) hbuf[i] = 0.0f;
        __syncthreads();
        for (int i = tid; i < Kin * 200; i += THREADS) {
            int k = i / 200, n = i - k * 200;
            Wt[n * KP + k] = W[i];           // transposed, coalesced global read
        }
        for (int i = tid; i < HID * 200; i += THREADS) {
            int k = i / 200, n = i - k * 200;
            Ut[n * KP + k] = U[i];
        }
        for (int i = tid; i < 200; i += THREADS) bias[i] = bv[i];
        __syncthreads();

        if (layer == 0)
            lstm_steps<2>(seq, hbuf, Wt, Ut, bias, b, j, true);
        else if (layer < 3)
            lstm_steps<NK4>(seq, hbuf, Wt, Ut, bias, b, j, true);
        else
            lstm_steps<NK4>(seq, hbuf, Wt, Ut, bias, b, j, false);  // only last h
    }

    // ---- Dense(50) + Dense(1, sigmoid) ----
    for (int i = tid; i < 10400; i += THREADS) Wt[i] = 0.0f;
    __syncthreads();
    for (int i = tid; i < HID * HID; i += THREADS) {
        int k = i / HID, m = i - k * HID;
        Wt[m * KP + k] = p.Wd1[i];
    }
    for (int i = tid; i < HID; i += THREADS) {
        bias[i] = p.bd1[i];
        wd2[i]  = p.Wd2[i];
    }
    if (tid == 0) wd2[HID] = p.bd2[0];
    __syncthreads();

    {
        const ulonglong2* Wt2 = (const ulonglong2*)Wt;
        const ulonglong2* h2  = (const ulonglong2*)hbuf;
        u64 a0 = 0;
#pragma unroll 2
        for (int k4 = 0; k4 < NK4; k4++) {
            ulonglong2 hv = h2[b * NK4 + k4];
            ulonglong2 wv = Wt2[j * NK4 + k4];
            ffma2(a0, hv.x, wv.x);
            ffma2(a0, hv.y, wv.y);
        }
        seq[b * SEQSTR + j] = bias[j] + hsum2(a0);  // dense1 out
    }
    __syncthreads();

    if (j == 0 && valid) {
        float acc = wd2[HID];  // bd2
#pragma unroll
        for (int m = 0; m < HID; m++) acc += seq[b * SEQSTR + m] * wd2[m];
        p.out[bg] = sigmoid_(acc);
    }
}

extern "C" void kernel_launch(void* const* d_in, const int* in_sizes, int n_in,
                              void* d_out, int out_size) {
    Params p;
    p.x = (const float*)d_in[0];
    p.W[0] = (const float*)d_in[1];  p.U[0] = (const float*)d_in[2];  p.bb[0] = (const float*)d_in[3];
    p.W[1] = (const float*)d_in[4];  p.U[1] = (const float*)d_in[5];  p.bb[1] = (const float*)d_in[6];
    p.W[2] = (const float*)d_in[7];  p.U[2] = (const float*)d_in[8];  p.bb[2] = (const float*)d_in[9];
    p.W[3] = (const float*)d_in[10]; p.U[3] = (const float*)d_in[11]; p.bb[3] = (const float*)d_in[12];
    p.Wd1 = (const float*)d_in[13];
    p.bd1 = (const float*)d_in[14];
    p.Wd2 = (const float*)d_in[15];
    p.bd2 = (const float*)d_in[16];
    p.out = (float*)d_out;
    p.B = in_sizes[0] / (TT * 5);

    cudaFuncSetAttribute(lstm_fused, cudaFuncAttributeMaxDynamicSharedMemorySize, SMEM_BYTES);
    int grid = (p.B + NB - 1) / NB;
    lstm_fused<<<grid, THREADS, SMEM_BYTES>>>(p);
}